// round 6
// baseline (speedup 1.0000x reference)
#include <cuda_runtime.h>
#include <cuda_bf16.h>

// Chamfer distance, B=16, N=M=2048, D=3 — single kernel, PPT=8.
// Diagnosis R5: kernel was smem-crossbar-bound (each LDS.128 delivers 512B =
// ~4 crossbar cyc/SM, broadcast or not; 2.1M of them = the whole runtime).
// Fix: 8 query points per thread -> each 32B packed-ref fetch covers 512
// point-pairs per warp; LDS drops 4x, fma pipe (3 FFMA2 / 2 pairs) now binds.
// Cross-block combine unchanged from R4/R5: atomicMax on order-reversed float
// encoding (max-identity 0 -> zero-init scratch, self-resetting, replay-safe).

#define CH_NPTS   2048
#define CH_B      16
#define CH_CHUNKS 16
#define CH_REFS   (CH_NPTS / CH_CHUNKS)     // 128 refs per chunk
#define CH_PAIRS  (CH_REFS / 2)             // 64 packed ref pairs
#define CH_TPB    128
#define CH_PPT    8
#define CH_PTSBLK (CH_TPB * CH_PPT)         // 1024
#define CH_GRIDX  (CH_NPTS / CH_PTSBLK)     // 2
#define CH_GROUPS (2 * CH_B)                // 32
#define CH_BLKS_PER_GROUP (CH_GRIDX * CH_CHUNKS)  // 32

__device__ unsigned g_ws[CH_GROUPS * CH_NPTS];   // encR minima; 0 = identity
__device__ unsigned g_cnt[CH_GROUPS];            // zero-init, self-reset
__device__ float    g_sum[CH_GROUPS];
__device__ unsigned g_cnt2;                      // zero-init, self-reset

__device__ __forceinline__ unsigned long long f32x2_fma(
    unsigned long long a, unsigned long long b, unsigned long long c) {
    unsigned long long d;
    asm("fma.rn.f32x2 %0, %1, %2, %3;" : "=l"(d) : "l"(a), "l"(b), "l"(c));
    return d;
}
__device__ __forceinline__ void f32x2_unpack(unsigned long long v, float& lo, float& hi) {
    asm("mov.b64 {%0, %1}, %2;" : "=f"(lo), "=f"(hi) : "l"(v));
}
__device__ __forceinline__ unsigned long long f32x2_pack(float lo, float hi) {
    unsigned long long v;
    asm("mov.b64 %0, {%1, %2};" : "=l"(v) : "f"(lo), "f"(hi));
    return v;
}

// Order-REVERSED encode: smaller float -> LARGER code; max-identity = 0.
__device__ __forceinline__ unsigned encR(float f) {
    unsigned u = __float_as_uint(f);
    unsigned e = (u & 0x80000000u) ? ~u : (u | 0x80000000u);
    return ~e;
}
__device__ __forceinline__ float decR(unsigned r) {
    unsigned e = ~r;
    return (e & 0x80000000u) ? __uint_as_float(e ^ 0x80000000u)
                             : __uint_as_float(~e);
}

__global__ __launch_bounds__(CH_TPB)
void chamfer_kernel(const float* __restrict__ preds,
                    const float* __restrict__ targs,
                    float* __restrict__ out)
{
    __shared__ ulonglong2 sA[CH_PAIRS];   // { pack(-2r0,-2r0'), pack(-2r1,-2r1') }
    __shared__ ulonglong2 sB[CH_PAIRS];   // { pack(-2r2,-2r2'), pack(|r|^2,|r'|^2) }
    __shared__ unsigned   sTicket;
    __shared__ float      sRed[CH_TPB / 32];

    const int dir = blockIdx.z >> 4;
    const int c   = blockIdx.z & 15;
    const int b   = blockIdx.y;
    const int grp = dir * CH_B + b;
    const float* __restrict__ pts  = dir ? targs : preds;
    const float* __restrict__ refs = dir ? preds : targs;

    // ---- stage packed, pre-scaled refs for this chunk ----
    const float* refB = refs + ((size_t)b * CH_NPTS + c * CH_REFS) * 3;
    if (threadIdx.x < CH_PAIRS) {
        int jj = threadIdx.x;
        const float* r = refB + jj * 6;
        float a0 = r[0], a1 = r[1], a2 = r[2];
        float c0 = r[3], c1 = r[4], c2 = r[5];
        sA[jj] = make_ulonglong2(f32x2_pack(-2.0f * a0, -2.0f * c0),
                                 f32x2_pack(-2.0f * a1, -2.0f * c1));
        sB[jj] = make_ulonglong2(f32x2_pack(-2.0f * a2, -2.0f * c2),
                                 f32x2_pack(fmaf(a0, a0, fmaf(a1, a1, a2 * a2)),
                                            fmaf(c0, c0, fmaf(c1, c1, c2 * c2))));
    }
    __syncthreads();

    // ---- query points (8 per thread, broadcast-packed) ----
    unsigned long long q0[CH_PPT], q1[CH_PPT], q2[CH_PPT];
    const float* ptsB = pts + (size_t)b * CH_NPTS * 3;
    const int pbase = blockIdx.x * CH_PTSBLK + threadIdx.x;
    #pragma unroll
    for (int k = 0; k < CH_PPT; ++k) {
        int p = pbase + k * CH_TPB;
        float x0 = ptsB[p * 3 + 0];
        float x1 = ptsB[p * 3 + 1];
        float x2 = ptsB[p * 3 + 2];
        q0[k] = f32x2_pack(x0, x0);
        q1[k] = f32x2_pack(x1, x1);
        q2[k] = f32x2_pack(x2, x2);
    }

    float mlo[CH_PPT], mhi[CH_PPT];
    #pragma unroll
    for (int k = 0; k < CH_PPT; ++k) { mlo[k] = 3.402823466e38f; mhi[k] = 3.402823466e38f; }

    #pragma unroll 4
    for (int jj = 0; jj < CH_PAIRS; ++jj) {
        ulonglong2 ra = sA[jj];   // 2x LDS.128, amortized over 512 pairs/warp
        ulonglong2 rb = sB[jj];
        #pragma unroll
        for (int k = 0; k < CH_PPT; ++k) {
            unsigned long long t = f32x2_fma(q2[k], rb.x, rb.y);
            t = f32x2_fma(q1[k], ra.y, t);
            t = f32x2_fma(q0[k], ra.x, t);
            float lo, hi;
            f32x2_unpack(t, lo, hi);      // free: register-pair alias
            mlo[k] = fminf(mlo[k], lo);
            mhi[k] = fminf(mhi[k], hi);
        }
    }

    // ---- publish per-point chunk minima (REDG.MAX on reversed encoding) ----
    unsigned* wsB = g_ws + (size_t)grp * CH_NPTS;
    #pragma unroll
    for (int k = 0; k < CH_PPT; ++k)
        atomicMax(&wsB[pbase + k * CH_TPB], encR(fminf(mlo[k], mhi[k])));

    __threadfence();
    __syncthreads();
    if (threadIdx.x == 0)
        sTicket = atomicAdd(&g_cnt[grp], 1u);
    __syncthreads();

    if (sTicket != CH_BLKS_PER_GROUP - 1) return;

    // ---- group finalize (last block of this (dir,b) group) ----
    __threadfence();
    float acc = 0.0f;
    for (int p = threadIdx.x; p < CH_NPTS; p += CH_TPB) {
        float m  = decR(wsB[p]);
        wsB[p] = 0u;                       // reset identity for next replay
        float x0 = ptsB[p * 3 + 0];
        float x1 = ptsB[p * 3 + 1];
        float x2 = ptsB[p * 3 + 2];
        acc += fmaf(x0, x0, fmaf(x1, x1, x2 * x2)) + m;
    }
    #pragma unroll
    for (int o = 16; o > 0; o >>= 1)
        acc += __shfl_down_sync(0xffffffffu, acc, o);
    if ((threadIdx.x & 31) == 0) sRed[threadIdx.x >> 5] = acc;
    __syncthreads();

    if (threadIdx.x == 0) {
        g_sum[grp] = sRed[0] + sRed[1] + sRed[2] + sRed[3];
        g_cnt[grp] = 0u;
        __threadfence();
        unsigned t2 = atomicAdd(&g_cnt2, 1u);
        if (t2 == CH_GROUPS - 1) {
            __threadfence();
            float s = 0.0f;
            #pragma unroll
            for (int i = 0; i < CH_GROUPS; ++i) s += g_sum[i];
            out[0] = s;
            g_cnt2 = 0u;
        }
    }
}

extern "C" void kernel_launch(void* const* d_in, const int* in_sizes, int n_in,
                              void* d_out, int out_size) {
    const float* preds = (const float*)d_in[0];
    const float* targs = (const float*)d_in[1];
    float* out = (float*)d_out;

    dim3 grid(CH_GRIDX, CH_B, 2 * CH_CHUNKS);   // (2, 16, 32) = 1024 blocks
    chamfer_kernel<<<grid, CH_TPB>>>(preds, targs, out);
}

// round 8
// speedup vs baseline: 1.2940x; 1.2940x over previous
#include <cuda_runtime.h>
#include <cuda_bf16.h>

// Chamfer distance, B=16, N=M=2048, D=3 — two-kernel split (R3-proven
// structure, minus init kernel and minus atomics in the hot path).
// Partial kernel: each block = one 512-ref chunk vs 256 query points.
// Refs pre-scaled by -2 with |y|^2 precomputed, 2 refs packed per 64-bit
// lane; inner body = 3x fma.rn.f32x2 + free unpack + 2x FMNMX per 2 pairs.
// Per-chunk minima published with PLAIN stores (scratch fully overwritten
// every launch -> no init kernel, no atomics, no fences). Finalize kernel
// min-combines 4 chunks, adds |x|^2, block-reduces, atomicAdds into out[0]
// (zeroed by the partial kernel; safe via stream ordering).

#define CH_NPTS   2048
#define CH_B      16
#define CH_CHUNKS 4
#define CH_REFS   (CH_NPTS / CH_CHUNKS)     // 512 refs per chunk
#define CH_PAIRS  (CH_REFS / 2)             // 256 packed ref pairs
#define CH_TPB    128
#define CH_PPT    2
#define CH_PTSBLK (CH_TPB * CH_PPT)         // 256
#define CH_GRIDX  (CH_NPTS / CH_PTSBLK)     // 8
#define CH_GROUPS (2 * CH_B)                // 32

__device__ float g_ws[CH_GROUPS * CH_CHUNKS * CH_NPTS];   // chunk minima (1 MB)

__device__ __forceinline__ unsigned long long f32x2_fma(
    unsigned long long a, unsigned long long b, unsigned long long c) {
    unsigned long long d;
    asm("fma.rn.f32x2 %0, %1, %2, %3;" : "=l"(d) : "l"(a), "l"(b), "l"(c));
    return d;
}
__device__ __forceinline__ void f32x2_unpack(unsigned long long v, float& lo, float& hi) {
    asm("mov.b64 {%0, %1}, %2;" : "=f"(lo), "=f"(hi) : "l"(v));
}
__device__ __forceinline__ unsigned long long f32x2_pack(float lo, float hi) {
    unsigned long long v;
    asm("mov.b64 %0, {%1, %2};" : "=l"(v) : "f"(lo), "f"(hi));
    return v;
}

__global__ __launch_bounds__(CH_TPB)
void chamfer_partial(const float* __restrict__ preds,
                     const float* __restrict__ targs,
                     float* __restrict__ out)
{
    __shared__ ulonglong2 sA[CH_PAIRS];   // { pack(-2r0,-2r0'), pack(-2r1,-2r1') }
    __shared__ ulonglong2 sB[CH_PAIRS];   // { pack(-2r2,-2r2'), pack(|r|^2,|r'|^2) }

    const int dir = blockIdx.z >> 2;
    const int c   = blockIdx.z & 3;
    const int b   = blockIdx.y;
    const int grp = dir * CH_B + b;
    const float* __restrict__ pts  = dir ? targs : preds;
    const float* __restrict__ refs = dir ? preds : targs;

    // Zero the output once per launch (finalize runs after us in stream order).
    if (blockIdx.x == 0 && blockIdx.y == 0 && blockIdx.z == 0 && threadIdx.x == 0)
        out[0] = 0.0f;

    // ---- stage packed, pre-scaled refs for this chunk ----
    const float* refB = refs + ((size_t)b * CH_NPTS + c * CH_REFS) * 3;
    for (int jj = threadIdx.x; jj < CH_PAIRS; jj += CH_TPB) {
        const float* r = refB + jj * 6;
        float a0 = r[0], a1 = r[1], a2 = r[2];
        float c0 = r[3], c1 = r[4], c2 = r[5];
        sA[jj] = make_ulonglong2(f32x2_pack(-2.0f * a0, -2.0f * c0),
                                 f32x2_pack(-2.0f * a1, -2.0f * c1));
        sB[jj] = make_ulonglong2(f32x2_pack(-2.0f * a2, -2.0f * c2),
                                 f32x2_pack(fmaf(a0, a0, fmaf(a1, a1, a2 * a2)),
                                            fmaf(c0, c0, fmaf(c1, c1, c2 * c2))));
    }
    __syncthreads();

    // ---- query points ----
    unsigned long long q0[CH_PPT], q1[CH_PPT], q2[CH_PPT];
    const float* ptsB = pts + (size_t)b * CH_NPTS * 3;
    const int pbase = blockIdx.x * CH_PTSBLK + threadIdx.x;
    #pragma unroll
    for (int k = 0; k < CH_PPT; ++k) {
        int p = pbase + k * CH_TPB;
        float x0 = ptsB[p * 3 + 0];
        float x1 = ptsB[p * 3 + 1];
        float x2 = ptsB[p * 3 + 2];
        q0[k] = f32x2_pack(x0, x0);
        q1[k] = f32x2_pack(x1, x1);
        q2[k] = f32x2_pack(x2, x2);
    }

    float mlo[CH_PPT], mhi[CH_PPT];
    #pragma unroll
    for (int k = 0; k < CH_PPT; ++k) { mlo[k] = 3.402823466e38f; mhi[k] = 3.402823466e38f; }

    #pragma unroll 8
    for (int jj = 0; jj < CH_PAIRS; ++jj) {
        ulonglong2 ra = sA[jj];   // LDS.128 broadcast
        ulonglong2 rb = sB[jj];   // LDS.128 broadcast
        #pragma unroll
        for (int k = 0; k < CH_PPT; ++k) {
            unsigned long long t = f32x2_fma(q2[k], rb.x, rb.y);
            t = f32x2_fma(q1[k], ra.y, t);
            t = f32x2_fma(q0[k], ra.x, t);
            float lo, hi;
            f32x2_unpack(t, lo, hi);           // free register-pair alias
            mlo[k] = fminf(mlo[k], lo);        // FMNMX (alu pipe)
            mhi[k] = fminf(mhi[k], hi);
        }
    }

    // ---- publish chunk minima (plain stores; fully rewritten every launch) ----
    float* wsC = g_ws + ((size_t)grp * CH_CHUNKS + c) * CH_NPTS;
    #pragma unroll
    for (int k = 0; k < CH_PPT; ++k)
        wsC[pbase + k * CH_TPB] = fminf(mlo[k], mhi[k]);
}

__global__ __launch_bounds__(256)
void chamfer_finalize(const float* __restrict__ preds,
                      const float* __restrict__ targs,
                      float* __restrict__ out)
{
    __shared__ float sRed[8];
    const int dir = blockIdx.z;
    const int b   = blockIdx.y;
    const int grp = dir * CH_B + b;
    const int p   = blockIdx.x * 256 + threadIdx.x;
    const float* pts = dir ? targs : preds;

    const float* wsG = g_ws + (size_t)grp * CH_CHUNKS * CH_NPTS;
    float m = fminf(fminf(wsG[p], wsG[CH_NPTS + p]),
                    fminf(wsG[2 * CH_NPTS + p], wsG[3 * CH_NPTS + p]));

    const float* xp = pts + ((size_t)b * CH_NPTS + p) * 3;
    float x0 = xp[0], x1 = xp[1], x2 = xp[2];
    float val = fmaf(x0, x0, fmaf(x1, x1, x2 * x2)) + m;

    #pragma unroll
    for (int o = 16; o > 0; o >>= 1)
        val += __shfl_down_sync(0xffffffffu, val, o);
    if ((threadIdx.x & 31) == 0) sRed[threadIdx.x >> 5] = val;
    __syncthreads();
    if (threadIdx.x < 32) {
        float v2 = (threadIdx.x < 8) ? sRed[threadIdx.x] : 0.0f;
        #pragma unroll
        for (int o = 4; o > 0; o >>= 1)
            v2 += __shfl_down_sync(0xffffffffu, v2, o);
        if (threadIdx.x == 0) atomicAdd(out, v2);
    }
}

extern "C" void kernel_launch(void* const* d_in, const int* in_sizes, int n_in,
                              void* d_out, int out_size) {
    const float* preds = (const float*)d_in[0];
    const float* targs = (const float*)d_in[1];
    float* out = (float*)d_out;

    dim3 gridP(CH_GRIDX, CH_B, 2 * CH_CHUNKS);   // (8, 16, 8) = 1024 blocks
    chamfer_partial<<<gridP, CH_TPB>>>(preds, targs, out);

    dim3 gridF(CH_NPTS / 256, CH_B, 2);          // (8, 16, 2) = 256 blocks
    chamfer_finalize<<<gridF, 256>>>(preds, targs, out);
}